// round 9
// baseline (speedup 1.0000x reference)
#include <cuda_runtime.h>
#include <cuda_fp16.h>
#include <mma.h>
#include <math.h>
#include <stdint.h>

using namespace nvcuda;

#define BATCH 2
#define NPTS  16384
#define KNB   32
#define C     128
#define MTOT  (BATCH*NPTS)   // 32768
#define NCTA  (MTOT/128)     // 256
#define LN_EPS 1e-5f

// scratch (device globals; no runtime allocation)
__device__ __half g_h [(size_t)MTOT*C];   // 8 MB, s in fp16
__device__ float  g_A [3*C];
__device__ float  g_wd[C];
__device__ float  g_b2[C];
__device__ unsigned long long g_bar;      // monotonic barrier counter (zero-init)

#define ALD 136                     // a/b smem pitch in halves (272 B)
#define CLD 132                     // c  smem pitch in floats (528 B)
#define DYN_SMEM ((128*CLD + 128 + 128 + 256 + 256) * 4)   // 70656 B

// ---------------------------------------------------------------------------
// One fused kernel: GEMM1 (wmma, Bm folded into A) -> grid barrier ->
// pool + GEMM2 (wmma) + bias + LayerNorm + relu.
// ---------------------------------------------------------------------------
__global__ __launch_bounds__(256, 2) void k_all(
    const float* __restrict__ pts,  const float* __restrict__ feat,
    const int*   __restrict__ gidx,
    const float* __restrict__ w_pos, const float* __restrict__ b_pos,
    const float* __restrict__ wg,    const float* __restrict__ b_gcm,
    const float* __restrict__ wout,  const float* __restrict__ bout,
    const float* __restrict__ lng,   const float* __restrict__ lnb,
    float* __restrict__ out)
{
    extern __shared__ char dyn[];
    __half* a_sm = (__half*)dyn;                    // [128][ALD]
    __half* b_sm = (__half*)dyn + 128*ALD;          // [128][ALD]

    __shared__ float wp_c[3][C];          // combined w_pos rows (neighbor coeffs)
    __shared__ float prep_part[8*256];    // CTA0 prep partials
    __shared__ unsigned long long s_target;

    const int tid  = threadIdx.x;
    const int wid  = tid >> 5;
    const int lane = tid & 31;
    const int row0 = blockIdx.x * 128;

    // ---- stage wp_c: neighbor-coefficient rows of w_pos ----
    if (tid < C) {
#pragma unroll
        for (int d = 0; d < 3; d++)
            wp_c[d][tid] = w_pos[(3+d)*C + tid] + w_pos[(6+d)*C + tid];
    }
    __syncthreads();

    // ---- Phase 1 stage: A = fp16(feat + pts·wp), B = fp16(w_gcm) ----
#pragma unroll
    for (int it = 0; it < 16; it++) {
        int idx = tid + it * 256;            // 4096 float4s over 128x128
        int r = idx >> 5, c4 = (idx & 31) << 2;
        int gr = row0 + r;
        float4 v = *(const float4*)&feat[(size_t)gr*C + c4];
        float px = pts[gr*3 + 0], py = pts[gr*3 + 1], pz = pts[gr*3 + 2];
        float4 w0 = *(const float4*)&wp_c[0][c4];
        float4 w1 = *(const float4*)&wp_c[1][c4];
        float4 w2 = *(const float4*)&wp_c[2][c4];
        v.x = fmaf(px, w0.x, fmaf(py, w1.x, fmaf(pz, w2.x, v.x)));
        v.y = fmaf(px, w0.y, fmaf(py, w1.y, fmaf(pz, w2.y, v.y)));
        v.z = fmaf(px, w0.z, fmaf(py, w1.z, fmaf(pz, w2.z, v.z)));
        v.w = fmaf(px, w0.w, fmaf(py, w1.w, fmaf(pz, w2.w, v.w)));
        __half2 h0 = __floats2half2_rn(v.x, v.y);
        __half2 h1 = __floats2half2_rn(v.z, v.w);
        uint2 o; o.x = *(unsigned*)&h0; o.y = *(unsigned*)&h1;
        *(uint2*)&a_sm[r*ALD + c4] = o;

        float4 w = *(const float4*)&wg[(size_t)r*C + c4];
        __half2 q0 = __floats2half2_rn(w.x, w.y);
        __half2 q1 = __floats2half2_rn(w.z, w.w);
        uint2 ow; ow.x = *(unsigned*)&q0; ow.y = *(unsigned*)&q1;
        *(uint2*)&b_sm[r*ALD + c4] = ow;
    }
    __syncthreads();

    // ---- Phase 1 wmma: s-tile = e @ w_gcm ----
    const int wm = wid >> 1;     // 0..3 -> rows 32*wm
    const int wn = wid & 1;      // 0..1 -> cols 64*wn
    {
        wmma::fragment<wmma::accumulator, 16, 16, 16, float> acc[2][4];
#pragma unroll
        for (int i = 0; i < 2; i++)
#pragma unroll
            for (int j = 0; j < 4; j++) wmma::fill_fragment(acc[i][j], 0.f);

#pragma unroll
        for (int kk = 0; kk < 8; kk++) {
            wmma::fragment<wmma::matrix_a, 16, 16, 16, __half, wmma::row_major> af[2];
            wmma::fragment<wmma::matrix_b, 16, 16, 16, __half, wmma::row_major> bf[4];
#pragma unroll
            for (int i = 0; i < 2; i++)
                wmma::load_matrix_sync(af[i], &a_sm[(wm*32 + i*16)*ALD + kk*16], ALD);
#pragma unroll
            for (int j = 0; j < 4; j++)
                wmma::load_matrix_sync(bf[j], &b_sm[(kk*16)*ALD + wn*64 + j*16], ALD);
#pragma unroll
            for (int i = 0; i < 2; i++)
#pragma unroll
                for (int j = 0; j < 4; j++)
                    wmma::mma_sync(acc[i][j], af[i], bf[j], acc[i][j]);
        }
        __syncthreads();

        float* c_sm = (float*)dyn;                   // [128][CLD]
#pragma unroll
        for (int i = 0; i < 2; i++)
#pragma unroll
            for (int j = 0; j < 4; j++)
                wmma::store_matrix_sync(&c_sm[(wm*32 + i*16)*CLD + wn*64 + j*16],
                                        acc[i][j], CLD, wmma::mem_row_major);
        __syncthreads();

        // store s tile to g_h (fp16)
#pragma unroll
        for (int it = 0; it < 16; it++) {
            int idx = tid + it * 256;
            int r = idx >> 5, c4 = (idx & 31) << 2;
            float4 v = *(const float4*)&c_sm[r*CLD + c4];
            __half2 h0 = __floats2half2_rn(v.x, v.y);
            __half2 h1 = __floats2half2_rn(v.z, v.w);
            uint2 o; o.x = *(unsigned*)&h0; o.y = *(unsigned*)&h1;
            *(uint2*)&g_h[(size_t)(row0 + r)*C + c4] = o;
        }
    }
    __syncthreads();

    // ---- CTA 0: compute pool constants (A, wd, b2) in fp32 ----
    if (blockIdx.x == 0) {
        const int c    = tid & 127;
        const int half = tid >> 7;
        const int j0   = half * 64;
        float q[8];
#pragma unroll
        for (int i = 0; i < 8; i++) q[i] = 0.f;
#pragma unroll 4
        for (int jj = 0; jj < 64; jj++) {
            int j = j0 + jj;
            float w = wg[(size_t)j*C + c];
            q[0] = fmaf(w_pos[0*C + j], w, q[0]);
            q[1] = fmaf(w_pos[1*C + j], w, q[1]);
            q[2] = fmaf(w_pos[2*C + j], w, q[2]);
            q[3] = fmaf(w_pos[6*C + j], w, q[3]);
            q[4] = fmaf(w_pos[7*C + j], w, q[4]);
            q[5] = fmaf(w_pos[8*C + j], w, q[5]);
            q[6] = fmaf(w_pos[9*C + j], w, q[6]);
            q[7] = fmaf(b_pos[j],       w, q[7]);
        }
#pragma unroll
        for (int i = 0; i < 8; i++) prep_part[i*256 + tid] = q[i];
        __syncthreads();
        if (tid < 128) {
            float r[8];
#pragma unroll
            for (int i = 0; i < 8; i++)
                r[i] = prep_part[i*256 + tid] + prep_part[i*256 + tid + 128];
            g_A[0*C + tid] = r[0] - r[3];
            g_A[1*C + tid] = r[1] - r[4];
            g_A[2*C + tid] = r[2] - r[5];
            g_wd[tid]      = r[6];
            g_b2[tid]      = r[7] + b_gcm[tid];
        }
    }
    __syncthreads();

    // ---- grid barrier: arrive ----
    if (tid == 0) {
        __threadfence();
        unsigned long long old = atomicAdd(&g_bar, 1ULL);
        s_target = (old / (unsigned long long)NCTA + 1ULL) * (unsigned long long)NCTA;
    }
    __syncthreads();

    // ---- stage w_out fp16 while waiting (b_h region is free now) ----
    __half* a_h = (__half*)dyn;                     // [128][ALD]
    __half* b_h = (__half*)dyn + 128*ALD;           // [128][ALD]
#pragma unroll
    for (int it = 0; it < 16; it++) {
        int idx = tid + it * 256;
        int k = idx >> 5, c4 = (idx & 31) << 2;
        float4 v = *(const float4*)&wout[(size_t)k*C + c4];
        __half2 h0 = __floats2half2_rn(v.x, v.y);
        __half2 h1 = __floats2half2_rn(v.z, v.w);
        uint2 o; o.x = *(unsigned*)&h0; o.y = *(unsigned*)&h1;
        *(uint2*)&b_h[k*ALD + c4] = o;
    }

    // ---- grid barrier: wait ----
    if (tid == 0) {
        unsigned long long tgt = s_target;
        for (;;) {
            unsigned long long v;
            asm volatile("ld.acquire.gpu.u64 %0, [%1];" : "=l"(v) : "l"(&g_bar) : "memory");
            if (v >= tgt) break;
        }
    }
    __syncthreads();

    // ---- Phase 2 pool: 128 points, 2 at a time per warp -> fp16 a_h ----
    {
        const int c0 = lane << 2;
        const float4 wd = *(const float4*)&g_wd[c0];
        const float4 a0 = *(const float4*)&g_A[c0];
        const float4 a1 = *(const float4*)&g_A[C + c0];
        const float4 a2 = *(const float4*)&g_A[2*C + c0];
        const float4 b2 = *(const float4*)&g_b2[c0];

        for (int t = 0; t < 16; t += 2) {
            const int pl0 = wid * 16 + t;
            const int pl1 = pl0 + 1;
            const int pt0 = row0 + pl0;
            const int pt1 = row0 + pl1;
            const int base = (pt0 >> 14) << 14;

            const float cx0 = pts[pt0*3 + 0], cy0 = pts[pt0*3 + 1], cz0 = pts[pt0*3 + 2];
            const float cx1 = pts[pt1*3 + 0], cy1 = pts[pt1*3 + 1], cz1 = pts[pt1*3 + 2];

            int j0 = gidx[pt0*KNB + lane] + base;
            int j1 = gidx[pt1*KNB + lane] + base;
            const float* gp0 = &pts[(size_t)j0*3];
            const float* gp1 = &pts[(size_t)j1*3];
            float dx0 = gp0[0] - cx0, dy0 = gp0[1] - cy0, dz0 = gp0[2] - cz0;
            float dx1 = gp1[0] - cx1, dy1 = gp1[1] - cy1, dz1 = gp1[2] - cz1;
            float dist0 = sqrtf(fmaf(dx0, dx0, fmaf(dy0, dy0, dz0*dz0)));
            float dist1 = sqrtf(fmaf(dx1, dx1, fmaf(dy1, dy1, dz1*dz1)));

            float4 acc0 = make_float4(-3.0e38f, -3.0e38f, -3.0e38f, -3.0e38f);
            float4 acc1 = acc0;
#pragma unroll
            for (int k = 0; k < 32; k++) {
                int   jk0 = __shfl_sync(0xffffffffu, j0,    k);
                int   jk1 = __shfl_sync(0xffffffffu, j1,    k);
                float dk0 = __shfl_sync(0xffffffffu, dist0, k);
                float dk1 = __shfl_sync(0xffffffffu, dist1, k);
                uint2 raw0 = *(const uint2*)&g_h[(size_t)jk0*C + c0];
                uint2 raw1 = *(const uint2*)&g_h[(size_t)jk1*C + c0];
                float2 p01 = __half22float2(*(__half2*)&raw0.x);
                float2 p23 = __half22float2(*(__half2*)&raw0.y);
                float2 q01 = __half22float2(*(__half2*)&raw1.x);
                float2 q23 = __half22float2(*(__half2*)&raw1.y);
                acc0.x = fmaxf(acc0.x, fmaf(dk0, wd.x, p01.x));
                acc0.y = fmaxf(acc0.y, fmaf(dk0, wd.y, p01.y));
                acc0.z = fmaxf(acc0.z, fmaf(dk0, wd.z, p23.x));
                acc0.w = fmaxf(acc0.w, fmaf(dk0, wd.w, p23.y));
                acc1.x = fmaxf(acc1.x, fmaf(dk1, wd.x, q01.x));
                acc1.y = fmaxf(acc1.y, fmaf(dk1, wd.y, q01.y));
                acc1.z = fmaxf(acc1.z, fmaf(dk1, wd.z, q23.x));
                acc1.w = fmaxf(acc1.w, fmaf(dk1, wd.w, q23.y));
            }

            const float4 f0 = *(const float4*)&feat[(size_t)pt0*C + c0];
            const float4 f1 = *(const float4*)&feat[(size_t)pt1*C + c0];
            float4 r0, r1;
            r0.x = fmaxf(acc0.x + fmaf(cx0, a0.x, fmaf(cy0, a1.x, fmaf(cz0, a2.x, b2.x))), 0.f) + f0.x;
            r0.y = fmaxf(acc0.y + fmaf(cx0, a0.y, fmaf(cy0, a1.y, fmaf(cz0, a2.y, b2.y))), 0.f) + f0.y;
            r0.z = fmaxf(acc0.z + fmaf(cx0, a0.z, fmaf(cy0, a1.z, fmaf(cz0, a2.z, b2.z))), 0.f) + f0.z;
            r0.w = fmaxf(acc0.w + fmaf(cx0, a0.w, fmaf(cy0, a1.w, fmaf(cz0, a2.w, b2.w))), 0.f) + f0.w;
            r1.x = fmaxf(acc1.x + fmaf(cx1, a0.x, fmaf(cy1, a1.x, fmaf(cz1, a2.x, b2.x))), 0.f) + f1.x;
            r1.y = fmaxf(acc1.y + fmaf(cx1, a0.y, fmaf(cy1, a1.y, fmaf(cz1, a2.y, b2.y))), 0.f) + f1.y;
            r1.z = fmaxf(acc1.z + fmaf(cx1, a0.z, fmaf(cy1, a1.z, fmaf(cz1, a2.z, b2.z))), 0.f) + f1.z;
            r1.w = fmaxf(acc1.w + fmaf(cx1, a0.w, fmaf(cy1, a1.w, fmaf(cz1, a2.w, b2.w))), 0.f) + f1.w;

            __half2 h0 = __floats2half2_rn(r0.x, r0.y);
            __half2 h1 = __floats2half2_rn(r0.z, r0.w);
            uint2 o0; o0.x = *(unsigned*)&h0; o0.y = *(unsigned*)&h1;
            *(uint2*)&a_h[pl0*ALD + c0] = o0;
            __half2 h2 = __floats2half2_rn(r1.x, r1.y);
            __half2 h3 = __floats2half2_rn(r1.z, r1.w);
            uint2 o1; o1.x = *(unsigned*)&h2; o1.y = *(unsigned*)&h3;
            *(uint2*)&a_h[pl1*ALD + c0] = o1;
        }
    }
    __syncthreads();

    // ---- Phase 2 wmma: res @ w_out ----
    wmma::fragment<wmma::accumulator, 16, 16, 16, float> acc[2][4];
#pragma unroll
    for (int i = 0; i < 2; i++)
#pragma unroll
        for (int j = 0; j < 4; j++) wmma::fill_fragment(acc[i][j], 0.f);

#pragma unroll
    for (int kk = 0; kk < 8; kk++) {
        wmma::fragment<wmma::matrix_a, 16, 16, 16, __half, wmma::row_major> af[2];
        wmma::fragment<wmma::matrix_b, 16, 16, 16, __half, wmma::row_major> bf[4];
#pragma unroll
        for (int i = 0; i < 2; i++)
            wmma::load_matrix_sync(af[i], &a_h[(wm*32 + i*16)*ALD + kk*16], ALD);
#pragma unroll
        for (int j = 0; j < 4; j++)
            wmma::load_matrix_sync(bf[j], &b_h[(kk*16)*ALD + wn*64 + j*16], ALD);
#pragma unroll
        for (int i = 0; i < 2; i++)
#pragma unroll
            for (int j = 0; j < 4; j++)
                wmma::mma_sync(acc[i][j], af[i], bf[j], acc[i][j]);
    }
    __syncthreads();

    // ---- epilogue: frags -> fp32 smem, bias + LN (256-thread stats) + relu ----
    float* c_sm = (float*)dyn;                      // [128][CLD]
    float* smu  = (float*)dyn + 128*CLD;            // [128]
    float* srs  = smu + 128;                        // [128]
    float* sp   = srs + 128;                        // [256]
    float* sq   = sp + 256;                         // [256]

#pragma unroll
    for (int i = 0; i < 2; i++)
#pragma unroll
        for (int j = 0; j < 4; j++)
            wmma::store_matrix_sync(&c_sm[(wm*32 + i*16)*CLD + wn*64 + j*16],
                                    acc[i][j], CLD, wmma::mem_row_major);
    __syncthreads();

    {
        int r = tid & 127, half = tid >> 7;
        int cbeg = half * 64;
        float sum = 0.f, ss = 0.f;
#pragma unroll 8
        for (int c = cbeg; c < cbeg + 64; c += 4) {
            float4 x = *(const float4*)&c_sm[r*CLD + c];
            float4 b = *(const float4*)&bout[c];
            float v0 = x.x + b.x, v1 = x.y + b.y, v2 = x.z + b.z, v3 = x.w + b.w;
            sum += v0 + v1 + v2 + v3;
            ss = fmaf(v0, v0, fmaf(v1, v1, fmaf(v2, v2, fmaf(v3, v3, ss))));
        }
        sp[tid] = sum; sq[tid] = ss;
    }
    __syncthreads();
    if (tid < 128) {
        float sum = sp[tid] + sp[tid + 128];
        float ss  = sq[tid] + sq[tid + 128];
        float mu  = sum * (1.f/128.f);
        float var = fmaf(ss, 1.f/128.f, -mu*mu);
        smu[tid] = mu;
        srs[tid] = rsqrtf(var + LN_EPS);
    }
    __syncthreads();

#pragma unroll
    for (int it = 0; it < 16; it++) {
        int idx = tid + it * 256;
        int r = idx >> 5, c4 = (idx & 31) << 2;
        float4 x = *(const float4*)&c_sm[r*CLD + c4];
        float4 bb = *(const float4*)&bout[c4];
        float4 g = *(const float4*)&lng[c4];
        float4 lb = *(const float4*)&lnb[c4];
        float mu = smu[r], rs = srs[r];
        float4 y;
        y.x = fmaxf(fmaf((x.x + bb.x - mu) * rs, g.x, lb.x), 0.f);
        y.y = fmaxf(fmaf((x.y + bb.y - mu) * rs, g.y, lb.y), 0.f);
        y.z = fmaxf(fmaf((x.z + bb.z - mu) * rs, g.z, lb.z), 0.f);
        y.w = fmaxf(fmaf((x.w + bb.w - mu) * rs, g.w, lb.w), 0.f);
        *(float4*)&out[(size_t)(row0 + r)*C + c4] = y;
    }
}

// ---------------------------------------------------------------------------
extern "C" void kernel_launch(void* const* d_in, const int* in_sizes, int n_in,
                              void* d_out, int out_size)
{
    const float* points = (const float*)d_in[0];
    const float* feat   = (const float*)d_in[1];
    const int*   gidx   = (const int*)  d_in[2];
    const float* w_pos  = (const float*)d_in[3];
    const float* b_pos  = (const float*)d_in[4];
    const float* w_gcm  = (const float*)d_in[5];
    const float* b_gcm  = (const float*)d_in[6];
    const float* w_out  = (const float*)d_in[7];
    const float* b_out  = (const float*)d_in[8];
    const float* ln_g   = (const float*)d_in[9];
    const float* ln_b   = (const float*)d_in[10];
    float* out = (float*)d_out;

    cudaFuncSetAttribute(k_all, cudaFuncAttributeMaxDynamicSharedMemorySize, DYN_SMEM);

    k_all<<<NCTA, 256, DYN_SMEM>>>(points, feat, gidx,
                                   w_pos, b_pos, w_gcm, b_gcm,
                                   w_out, b_out, ln_g, ln_b, out);
}

// round 10
// speedup vs baseline: 1.1115x; 1.1115x over previous
#include <cuda_runtime.h>
#include <cuda_fp16.h>
#include <mma.h>
#include <math.h>
#include <stdint.h>

using namespace nvcuda;

#define BATCH 2
#define NPTS  16384
#define KNB   32
#define C     128
#define MTOT  (BATCH*NPTS)   // 32768
#define LN_EPS 1e-5f

// scratch (device globals; no runtime allocation)
__device__ __half g_h [(size_t)MTOT*C];   // 8 MB, s in fp16
__device__ float  g_A [3*C];
__device__ float  g_wd[C];
__device__ float  g_b2[C];

#define ALD 136                     // a/b smem pitch in halves (272 B)
#define CLD 132                     // c  smem pitch in floats (528 B)
#define GS_SMEM  (2 * 128 * ALD * 2)                        // 69632 B
#define FUSED_SMEM ((128*CLD + 128 + 128 + 256 + 256) * 4)  // 70656 B

// ---------------------------------------------------------------------------
// K1 (wmma): s = (feat + pts·wp_nbr) @ w_gcm -> fp16 g_h.
// CTA 0 additionally computes pool constants g_A/g_wd/g_b2 afterwards.
// ---------------------------------------------------------------------------
__global__ __launch_bounds__(256, 2) void k_gemm_s(
    const float* __restrict__ feat, const float* __restrict__ wg,
    const float* __restrict__ pts,
    const float* __restrict__ w_pos, const float* __restrict__ b_pos,
    const float* __restrict__ b_gcm)
{
    extern __shared__ char dyn[];
    __half* a_sm = (__half*)dyn;                    // [128][ALD]
    __half* b_sm = (__half*)dyn + 128*ALD;          // [128][ALD]

    __shared__ float wp_c[3][C];

    const int tid  = threadIdx.x;
    const int wid  = tid >> 5;
    const int row0 = blockIdx.x * 128;

    if (tid < C) {
#pragma unroll
        for (int d = 0; d < 3; d++)
            wp_c[d][tid] = w_pos[(3+d)*C + tid] + w_pos[(6+d)*C + tid];
    }
    __syncthreads();

    // stage A = fp16(feat + pts·wp_c), B = fp16(w_gcm)
#pragma unroll
    for (int it = 0; it < 16; it++) {
        int idx = tid + it * 256;
        int r = idx >> 5, c4 = (idx & 31) << 2;
        int gr = row0 + r;
        float4 v = *(const float4*)&feat[(size_t)gr*C + c4];
        float px = pts[gr*3 + 0], py = pts[gr*3 + 1], pz = pts[gr*3 + 2];
        float4 w0 = *(const float4*)&wp_c[0][c4];
        float4 w1 = *(const float4*)&wp_c[1][c4];
        float4 w2 = *(const float4*)&wp_c[2][c4];
        v.x = fmaf(px, w0.x, fmaf(py, w1.x, fmaf(pz, w2.x, v.x)));
        v.y = fmaf(px, w0.y, fmaf(py, w1.y, fmaf(pz, w2.y, v.y)));
        v.z = fmaf(px, w0.z, fmaf(py, w1.z, fmaf(pz, w2.z, v.z)));
        v.w = fmaf(px, w0.w, fmaf(py, w1.w, fmaf(pz, w2.w, v.w)));
        __half2 h0 = __floats2half2_rn(v.x, v.y);
        __half2 h1 = __floats2half2_rn(v.z, v.w);
        uint2 o; o.x = *(unsigned*)&h0; o.y = *(unsigned*)&h1;
        *(uint2*)&a_sm[r*ALD + c4] = o;

        float4 w = *(const float4*)&wg[(size_t)r*C + c4];
        __half2 q0 = __floats2half2_rn(w.x, w.y);
        __half2 q1 = __floats2half2_rn(w.z, w.w);
        uint2 ow; ow.x = *(unsigned*)&q0; ow.y = *(unsigned*)&q1;
        *(uint2*)&b_sm[r*ALD + c4] = ow;
    }
    __syncthreads();

    const int wm = wid >> 1;
    const int wn = wid & 1;

    wmma::fragment<wmma::accumulator, 16, 16, 16, float> acc[2][4];
#pragma unroll
    for (int i = 0; i < 2; i++)
#pragma unroll
        for (int j = 0; j < 4; j++) wmma::fill_fragment(acc[i][j], 0.f);

#pragma unroll
    for (int kk = 0; kk < 8; kk++) {
        wmma::fragment<wmma::matrix_a, 16, 16, 16, __half, wmma::row_major> af[2];
        wmma::fragment<wmma::matrix_b, 16, 16, 16, __half, wmma::row_major> bf[4];
#pragma unroll
        for (int i = 0; i < 2; i++)
            wmma::load_matrix_sync(af[i], &a_sm[(wm*32 + i*16)*ALD + kk*16], ALD);
#pragma unroll
        for (int j = 0; j < 4; j++)
            wmma::load_matrix_sync(bf[j], &b_sm[(kk*16)*ALD + wn*64 + j*16], ALD);
#pragma unroll
        for (int i = 0; i < 2; i++)
#pragma unroll
            for (int j = 0; j < 4; j++)
                wmma::mma_sync(acc[i][j], af[i], bf[j], acc[i][j]);
    }
    __syncthreads();

    float* c_sm = (float*)dyn;                      // [128][CLD]
#pragma unroll
    for (int i = 0; i < 2; i++)
#pragma unroll
        for (int j = 0; j < 4; j++)
            wmma::store_matrix_sync(&c_sm[(wm*32 + i*16)*CLD + wn*64 + j*16],
                                    acc[i][j], CLD, wmma::mem_row_major);
    __syncthreads();

#pragma unroll
    for (int it = 0; it < 16; it++) {
        int idx = tid + it * 256;
        int r = idx >> 5, c4 = (idx & 31) << 2;
        float4 v = *(const float4*)&c_sm[r*CLD + c4];
        __half2 h0 = __floats2half2_rn(v.x, v.y);
        __half2 h1 = __floats2half2_rn(v.z, v.w);
        uint2 o; o.x = *(unsigned*)&h0; o.y = *(unsigned*)&h1;
        *(uint2*)&g_h[(size_t)(row0 + r)*C + c4] = o;
    }

    // ---- CTA 0: pool constants (fp32) ----
    if (blockIdx.x == 0) {
        float* part = (float*)dyn + 0;  // reuse smem: 8*256 floats (safe, post-sync)
        __syncthreads();
        const int cc   = tid & 127;
        const int half = tid >> 7;
        const int j0   = half * 64;
        float q[8];
#pragma unroll
        for (int i = 0; i < 8; i++) q[i] = 0.f;
#pragma unroll 4
        for (int jj = 0; jj < 64; jj++) {
            int j = j0 + jj;
            float w = wg[(size_t)j*C + cc];
            q[0] = fmaf(w_pos[0*C + j], w, q[0]);
            q[1] = fmaf(w_pos[1*C + j], w, q[1]);
            q[2] = fmaf(w_pos[2*C + j], w, q[2]);
            q[3] = fmaf(w_pos[6*C + j], w, q[3]);
            q[4] = fmaf(w_pos[7*C + j], w, q[4]);
            q[5] = fmaf(w_pos[8*C + j], w, q[5]);
            q[6] = fmaf(w_pos[9*C + j], w, q[6]);
            q[7] = fmaf(b_pos[j],       w, q[7]);
        }
#pragma unroll
        for (int i = 0; i < 8; i++) part[i*256 + tid] = q[i];
        __syncthreads();
        if (tid < 128) {
            float r[8];
#pragma unroll
            for (int i = 0; i < 8; i++)
                r[i] = part[i*256 + tid] + part[i*256 + tid + 128];
            g_A[0*C + tid] = r[0] - r[3];
            g_A[1*C + tid] = r[1] - r[4];
            g_A[2*C + tid] = r[2] - r[5];
            g_wd[tid]      = r[6];
            g_b2[tid]      = r[7] + b_gcm[tid];
        }
    }
}

// ---------------------------------------------------------------------------
// K2 (fused): pool (half2 math, 2-pt interleave) -> fp16 A-tile, wmma GEMM,
// bias + LayerNorm (256-thread stats) + relu.
// ---------------------------------------------------------------------------
__global__ __launch_bounds__(256, 2) void k_fused(
    const float* __restrict__ pts,  const float* __restrict__ feat,
    const int*   __restrict__ gidx,
    const float* __restrict__ wout, const float* __restrict__ bout,
    const float* __restrict__ lng,  const float* __restrict__ lnb,
    float* __restrict__ out)
{
    extern __shared__ char dyn[];
    __half* a_h = (__half*)dyn;                     // [128][ALD]
    __half* b_h = (__half*)dyn + 128*ALD;           // [128][ALD]

    const int tid  = threadIdx.x;
    const int wid  = tid >> 5;
    const int lane = tid & 31;
    const int row0 = blockIdx.x * 128;

    // ---- stage B: w_out fp32 -> fp16 smem ----
#pragma unroll
    for (int it = 0; it < 16; it++) {
        int idx = tid + it * 256;
        int k = idx >> 5, c4 = (idx & 31) << 2;
        float4 v = *(const float4*)&wout[(size_t)k*C + c4];
        __half2 h0 = __floats2half2_rn(v.x, v.y);
        __half2 h1 = __floats2half2_rn(v.z, v.w);
        uint2 o; o.x = *(unsigned*)&h0; o.y = *(unsigned*)&h1;
        *(uint2*)&b_h[k*ALD + c4] = o;
    }

    // ---- Phase A: pool 128 points, 2 at a time per warp, half2 math ----
    {
        const int c0 = lane << 2;
        const float4 wd = *(const float4*)&g_wd[c0];
        const float4 a0 = *(const float4*)&g_A[c0];
        const float4 a1 = *(const float4*)&g_A[C + c0];
        const float4 a2 = *(const float4*)&g_A[2*C + c0];
        const float4 b2 = *(const float4*)&g_b2[c0];
        const __half2 wd01 = __floats2half2_rn(wd.x, wd.y);
        const __half2 wd23 = __floats2half2_rn(wd.z, wd.w);
        const __half2 ninf = __half2half2(__ushort_as_half(0xFC00));
        const __half* hs = &g_h[0];

        for (int t = 0; t < 16; t += 2) {
            const int pl0 = wid * 16 + t;
            const int pl1 = pl0 + 1;
            const int pt0 = row0 + pl0;
            const int pt1 = row0 + pl1;
            const int base = (pt0 >> 14) << 14;

            const float cx0 = pts[pt0*3 + 0], cy0 = pts[pt0*3 + 1], cz0 = pts[pt0*3 + 2];
            const float cx1 = pts[pt1*3 + 0], cy1 = pts[pt1*3 + 1], cz1 = pts[pt1*3 + 2];

            int j0 = gidx[pt0*KNB + lane] + base;
            int j1 = gidx[pt1*KNB + lane] + base;
            const float* gp0 = &pts[(size_t)j0*3];
            const float* gp1 = &pts[(size_t)j1*3];
            float dx0 = gp0[0] - cx0, dy0 = gp0[1] - cy0, dz0 = gp0[2] - cz0;
            float dx1 = gp1[0] - cx1, dy1 = gp1[1] - cy1, dz1 = gp1[2] - cz1;
            float dist0 = sqrtf(fmaf(dx0, dx0, fmaf(dy0, dy0, dz0*dz0)));
            float dist1 = sqrtf(fmaf(dx1, dx1, fmaf(dy1, dy1, dz1*dz1)));

            __half2 acc0a = ninf, acc0b = ninf, acc1a = ninf, acc1b = ninf;
#pragma unroll
            for (int k = 0; k < 32; k++) {
                int   jk0 = __shfl_sync(0xffffffffu, j0,    k);
                int   jk1 = __shfl_sync(0xffffffffu, j1,    k);
                float dk0 = __shfl_sync(0xffffffffu, dist0, k);
                float dk1 = __shfl_sync(0xffffffffu, dist1, k);
                __half2 d0 = __float2half2_rn(dk0);
                __half2 d1 = __float2half2_rn(dk1);
                uint2 raw0 = *(const uint2*)(hs + (((unsigned)jk0 << 7) + c0));
                uint2 raw1 = *(const uint2*)(hs + (((unsigned)jk1 << 7) + c0));
                acc0a = __hmax2(acc0a, __hfma2(d0, wd01, *(__half2*)&raw0.x));
                acc0b = __hmax2(acc0b, __hfma2(d0, wd23, *(__half2*)&raw0.y));
                acc1a = __hmax2(acc1a, __hfma2(d1, wd01, *(__half2*)&raw1.x));
                acc1b = __hmax2(acc1b, __hfma2(d1, wd23, *(__half2*)&raw1.y));
            }

            float2 m0a = __half22float2(acc0a);
            float2 m0b = __half22float2(acc0b);
            float2 m1a = __half22float2(acc1a);
            float2 m1b = __half22float2(acc1b);

            const float4 f0 = *(const float4*)&feat[(size_t)pt0*C + c0];
            const float4 f1 = *(const float4*)&feat[(size_t)pt1*C + c0];
            float4 r0, r1;
            r0.x = fmaxf(m0a.x + fmaf(cx0, a0.x, fmaf(cy0, a1.x, fmaf(cz0, a2.x, b2.x))), 0.f) + f0.x;
            r0.y = fmaxf(m0a.y + fmaf(cx0, a0.y, fmaf(cy0, a1.y, fmaf(cz0, a2.y, b2.y))), 0.f) + f0.y;
            r0.z = fmaxf(m0b.x + fmaf(cx0, a0.z, fmaf(cy0, a1.z, fmaf(cz0, a2.z, b2.z))), 0.f) + f0.z;
            r0.w = fmaxf(m0b.y + fmaf(cx0, a0.w, fmaf(cy0, a1.w, fmaf(cz0, a2.w, b2.w))), 0.f) + f0.w;
            r1.x = fmaxf(m1a.x + fmaf(cx1, a0.x, fmaf(cy1, a1.x, fmaf(cz1, a2.x, b2.x))), 0.f) + f1.x;
            r1.y = fmaxf(m1a.y + fmaf(cx1, a0.y, fmaf(cy1, a1.y, fmaf(cz1, a2.y, b2.y))), 0.f) + f1.y;
            r1.z = fmaxf(m1b.x + fmaf(cx1, a0.z, fmaf(cy1, a1.z, fmaf(cz1, a2.z, b2.z))), 0.f) + f1.z;
            r1.w = fmaxf(m1b.y + fmaf(cx1, a0.w, fmaf(cy1, a1.w, fmaf(cz1, a2.w, b2.w))), 0.f) + f1.w;

            __half2 h0 = __floats2half2_rn(r0.x, r0.y);
            __half2 h1 = __floats2half2_rn(r0.z, r0.w);
            uint2 o0; o0.x = *(unsigned*)&h0; o0.y = *(unsigned*)&h1;
            *(uint2*)&a_h[pl0*ALD + c0] = o0;
            __half2 h2 = __floats2half2_rn(r1.x, r1.y);
            __half2 h3 = __floats2half2_rn(r1.z, r1.w);
            uint2 o1; o1.x = *(unsigned*)&h2; o1.y = *(unsigned*)&h3;
            *(uint2*)&a_h[pl1*ALD + c0] = o1;
        }
    }
    __syncthreads();

    // ---- Phase B: wmma GEMM res @ w_out ----
    const int wm = wid >> 1;
    const int wn = wid & 1;

    wmma::fragment<wmma::accumulator, 16, 16, 16, float> acc[2][4];
#pragma unroll
    for (int i = 0; i < 2; i++)
#pragma unroll
        for (int j = 0; j < 4; j++) wmma::fill_fragment(acc[i][j], 0.f);

#pragma unroll
    for (int kk = 0; kk < 8; kk++) {
        wmma::fragment<wmma::matrix_a, 16, 16, 16, __half, wmma::row_major> af[2];
        wmma::fragment<wmma::matrix_b, 16, 16, 16, __half, wmma::row_major> bf[4];
#pragma unroll
        for (int i = 0; i < 2; i++)
            wmma::load_matrix_sync(af[i], &a_h[(wm*32 + i*16)*ALD + kk*16], ALD);
#pragma unroll
        for (int j = 0; j < 4; j++)
            wmma::load_matrix_sync(bf[j], &b_h[(kk*16)*ALD + wn*64 + j*16], ALD);
#pragma unroll
        for (int i = 0; i < 2; i++)
#pragma unroll
            for (int j = 0; j < 4; j++)
                wmma::mma_sync(acc[i][j], af[i], bf[j], acc[i][j]);
    }
    __syncthreads();

    // ---- Phase C: frags -> fp32 smem, bias + LN (256-thread stats) + relu ----
    float* c_sm = (float*)dyn;                      // [128][CLD]
    float* smu  = (float*)dyn + 128*CLD;            // [128]
    float* srs  = smu + 128;                        // [128]
    float* sp   = srs + 128;                        // [256]
    float* sq   = sp + 256;                         // [256]

#pragma unroll
    for (int i = 0; i < 2; i++)
#pragma unroll
        for (int j = 0; j < 4; j++)
            wmma::store_matrix_sync(&c_sm[(wm*32 + i*16)*CLD + wn*64 + j*16],
                                    acc[i][j], CLD, wmma::mem_row_major);
    __syncthreads();

    {
        int r = tid & 127, half = tid >> 7;
        int cbeg = half * 64;
        float sum = 0.f, ss = 0.f;
#pragma unroll 8
        for (int c = cbeg; c < cbeg + 64; c += 4) {
            float4 x = *(const float4*)&c_sm[r*CLD + c];
            float4 b = *(const float4*)&bout[c];
            float v0 = x.x + b.x, v1 = x.y + b.y, v2 = x.z + b.z, v3 = x.w + b.w;
            sum += v0 + v1 + v2 + v3;
            ss = fmaf(v0, v0, fmaf(v1, v1, fmaf(v2, v2, fmaf(v3, v3, ss))));
        }
        sp[tid] = sum; sq[tid] = ss;
    }
    __syncthreads();
    if (tid < 128) {
        float sum = sp[tid] + sp[tid + 128];
        float ss  = sq[tid] + sq[tid + 128];
        float mu  = sum * (1.f/128.f);
        float var = fmaf(ss, 1.f/128.f, -mu*mu);
        smu[tid] = mu;
        srs[tid] = rsqrtf(var + LN_EPS);
    }
    __syncthreads();

#pragma unroll
    for (int it = 0; it < 16; it++) {
        int idx = tid + it * 256;
        int r = idx >> 5, c4 = (idx & 31) << 2;
        float4 x = *(const float4*)&c_sm[r*CLD + c4];
        float4 bb = *(const float4*)&bout[c4];
        float4 g = *(const float4*)&lng[c4];
        float4 lb = *(const float4*)&lnb[c4];
        float mu = smu[r], rs = srs[r];
        float4 y;
        y.x = fmaxf(fmaf((x.x + bb.x - mu) * rs, g.x, lb.x), 0.f);
        y.y = fmaxf(fmaf((x.y + bb.y - mu) * rs, g.y, lb.y), 0.f);
        y.z = fmaxf(fmaf((x.z + bb.z - mu) * rs, g.z, lb.z), 0.f);
        y.w = fmaxf(fmaf((x.w + bb.w - mu) * rs, g.w, lb.w), 0.f);
        *(float4*)&out[(size_t)(row0 + r)*C + c4] = y;
    }
}

// ---------------------------------------------------------------------------
extern "C" void kernel_launch(void* const* d_in, const int* in_sizes, int n_in,
                              void* d_out, int out_size)
{
    const float* points = (const float*)d_in[0];
    const float* feat   = (const float*)d_in[1];
    const int*   gidx   = (const int*)  d_in[2];
    const float* w_pos  = (const float*)d_in[3];
    const float* b_pos  = (const float*)d_in[4];
    const float* w_gcm  = (const float*)d_in[5];
    const float* b_gcm  = (const float*)d_in[6];
    const float* w_out  = (const float*)d_in[7];
    const float* b_out  = (const float*)d_in[8];
    const float* ln_g   = (const float*)d_in[9];
    const float* ln_b   = (const float*)d_in[10];
    float* out = (float*)d_out;

    cudaFuncSetAttribute(k_gemm_s, cudaFuncAttributeMaxDynamicSharedMemorySize, GS_SMEM);
    cudaFuncSetAttribute(k_fused,  cudaFuncAttributeMaxDynamicSharedMemorySize, FUSED_SMEM);

    k_gemm_s<<<MTOT/128, 256, GS_SMEM>>>(feat, w_gcm, points, w_pos, b_pos, b_gcm);
    k_fused <<<MTOT/128, 256, FUSED_SMEM>>>(points, feat, gidx,
                                            w_out, b_out, ln_g, ln_b, out);
}

// round 11
// speedup vs baseline: 1.1722x; 1.0546x over previous
#include <cuda_runtime.h>
#include <cuda_fp16.h>
#include <mma.h>
#include <math.h>
#include <stdint.h>

using namespace nvcuda;

#define BATCH 2
#define NPTS  16384
#define KNB   32
#define C     128
#define MTOT  (BATCH*NPTS)   // 32768
#define LN_EPS 1e-5f

// scratch (device globals; no runtime allocation)
__device__ __half g_h [(size_t)MTOT*C];   // 8 MB, s in fp16
__device__ float  g_A [3*C];
__device__ float  g_wd[C];
__device__ float  g_b2[C];

#define ALD 136                     // a/b smem pitch in halves (272 B)
#define CLD 132                     // c  smem pitch in floats (528 B)
#define GS_SMEM  (2 * 128 * ALD * 2)                        // 69632 B
#define FUSED_SMEM ((128*CLD + 128 + 128 + 256 + 256) * 4)  // 70656 B

// ---------------------------------------------------------------------------
// K1 (wmma): s = (feat + pts·wp_nbr) @ w_gcm -> fp16 g_h.
// CTA 0 additionally computes pool constants g_A/g_wd/g_b2 afterwards.
// ---------------------------------------------------------------------------
__global__ __launch_bounds__(256, 2) void k_gemm_s(
    const float* __restrict__ feat, const float* __restrict__ wg,
    const float* __restrict__ pts,
    const float* __restrict__ w_pos, const float* __restrict__ b_pos,
    const float* __restrict__ b_gcm)
{
    extern __shared__ char dyn[];
    __half* a_sm = (__half*)dyn;                    // [128][ALD]
    __half* b_sm = (__half*)dyn + 128*ALD;          // [128][ALD]

    __shared__ float wp_c[3][C];

    const int tid  = threadIdx.x;
    const int wid  = tid >> 5;
    const int row0 = blockIdx.x * 128;

    if (tid < C) {
#pragma unroll
        for (int d = 0; d < 3; d++)
            wp_c[d][tid] = w_pos[(3+d)*C + tid] + w_pos[(6+d)*C + tid];
    }
    __syncthreads();

    // stage A = fp16(feat + pts·wp_c), B = fp16(w_gcm)
#pragma unroll
    for (int it = 0; it < 16; it++) {
        int idx = tid + it * 256;
        int r = idx >> 5, c4 = (idx & 31) << 2;
        int gr = row0 + r;
        float4 v = *(const float4*)&feat[(size_t)gr*C + c4];
        float px = pts[gr*3 + 0], py = pts[gr*3 + 1], pz = pts[gr*3 + 2];
        float4 w0 = *(const float4*)&wp_c[0][c4];
        float4 w1 = *(const float4*)&wp_c[1][c4];
        float4 w2 = *(const float4*)&wp_c[2][c4];
        v.x = fmaf(px, w0.x, fmaf(py, w1.x, fmaf(pz, w2.x, v.x)));
        v.y = fmaf(px, w0.y, fmaf(py, w1.y, fmaf(pz, w2.y, v.y)));
        v.z = fmaf(px, w0.z, fmaf(py, w1.z, fmaf(pz, w2.z, v.z)));
        v.w = fmaf(px, w0.w, fmaf(py, w1.w, fmaf(pz, w2.w, v.w)));
        __half2 h0 = __floats2half2_rn(v.x, v.y);
        __half2 h1 = __floats2half2_rn(v.z, v.w);
        uint2 o; o.x = *(unsigned*)&h0; o.y = *(unsigned*)&h1;
        *(uint2*)&a_sm[r*ALD + c4] = o;

        float4 w = *(const float4*)&wg[(size_t)r*C + c4];
        __half2 q0 = __floats2half2_rn(w.x, w.y);
        __half2 q1 = __floats2half2_rn(w.z, w.w);
        uint2 ow; ow.x = *(unsigned*)&q0; ow.y = *(unsigned*)&q1;
        *(uint2*)&b_sm[r*ALD + c4] = ow;
    }
    __syncthreads();

    const int wm = wid >> 1;
    const int wn = wid & 1;

    wmma::fragment<wmma::accumulator, 16, 16, 16, float> acc[2][4];
#pragma unroll
    for (int i = 0; i < 2; i++)
#pragma unroll
        for (int j = 0; j < 4; j++) wmma::fill_fragment(acc[i][j], 0.f);

#pragma unroll
    for (int kk = 0; kk < 8; kk++) {
        wmma::fragment<wmma::matrix_a, 16, 16, 16, __half, wmma::row_major> af[2];
        wmma::fragment<wmma::matrix_b, 16, 16, 16, __half, wmma::row_major> bf[4];
#pragma unroll
        for (int i = 0; i < 2; i++)
            wmma::load_matrix_sync(af[i], &a_sm[(wm*32 + i*16)*ALD + kk*16], ALD);
#pragma unroll
        for (int j = 0; j < 4; j++)
            wmma::load_matrix_sync(bf[j], &b_sm[(kk*16)*ALD + wn*64 + j*16], ALD);
#pragma unroll
        for (int i = 0; i < 2; i++)
#pragma unroll
            for (int j = 0; j < 4; j++)
                wmma::mma_sync(acc[i][j], af[i], bf[j], acc[i][j]);
    }
    __syncthreads();

    float* c_sm = (float*)dyn;                      // [128][CLD]
#pragma unroll
    for (int i = 0; i < 2; i++)
#pragma unroll
        for (int j = 0; j < 4; j++)
            wmma::store_matrix_sync(&c_sm[(wm*32 + i*16)*CLD + wn*64 + j*16],
                                    acc[i][j], CLD, wmma::mem_row_major);
    __syncthreads();

#pragma unroll
    for (int it = 0; it < 16; it++) {
        int idx = tid + it * 256;
        int r = idx >> 5, c4 = (idx & 31) << 2;
        float4 v = *(const float4*)&c_sm[r*CLD + c4];
        __half2 h0 = __floats2half2_rn(v.x, v.y);
        __half2 h1 = __floats2half2_rn(v.z, v.w);
        uint2 o; o.x = *(unsigned*)&h0; o.y = *(unsigned*)&h1;
        *(uint2*)&g_h[(size_t)(row0 + r)*C + c4] = o;
    }

    // ---- CTA 0: pool constants (fp32) ----
    if (blockIdx.x == 0) {
        float* part = (float*)dyn;  // reuse smem: 8*256 floats (post-sync)
        __syncthreads();
        const int cc   = tid & 127;
        const int half = tid >> 7;
        const int j0   = half * 64;
        float q[8];
#pragma unroll
        for (int i = 0; i < 8; i++) q[i] = 0.f;
#pragma unroll 4
        for (int jj = 0; jj < 64; jj++) {
            int j = j0 + jj;
            float w = wg[(size_t)j*C + cc];
            q[0] = fmaf(w_pos[0*C + j], w, q[0]);
            q[1] = fmaf(w_pos[1*C + j], w, q[1]);
            q[2] = fmaf(w_pos[2*C + j], w, q[2]);
            q[3] = fmaf(w_pos[6*C + j], w, q[3]);
            q[4] = fmaf(w_pos[7*C + j], w, q[4]);
            q[5] = fmaf(w_pos[8*C + j], w, q[5]);
            q[6] = fmaf(w_pos[9*C + j], w, q[6]);
            q[7] = fmaf(b_pos[j],       w, q[7]);
        }
#pragma unroll
        for (int i = 0; i < 8; i++) part[i*256 + tid] = q[i];
        __syncthreads();
        if (tid < 128) {
            float r[8];
#pragma unroll
            for (int i = 0; i < 8; i++)
                r[i] = part[i*256 + tid] + part[i*256 + tid + 128];
            g_A[0*C + tid] = r[0] - r[3];
            g_A[1*C + tid] = r[1] - r[4];
            g_A[2*C + tid] = r[2] - r[5];
            g_wd[tid]      = r[6];
            g_b2[tid]      = r[7] + b_gcm[tid];
        }
    }
}

// ---------------------------------------------------------------------------
// K2 (fused): pool (16-lane rows, uint4 gathers, packed j+dist shfl) ->
// fp16 A-tile, wmma GEMM, bias + LayerNorm + relu.
// ---------------------------------------------------------------------------
__global__ __launch_bounds__(256, 2) void k_fused(
    const float* __restrict__ pts,  const float* __restrict__ feat,
    const int*   __restrict__ gidx,
    const float* __restrict__ wout, const float* __restrict__ bout,
    const float* __restrict__ lng,  const float* __restrict__ lnb,
    float* __restrict__ out)
{
    extern __shared__ char dyn[];
    __half* a_h = (__half*)dyn;                     // [128][ALD]
    __half* b_h = (__half*)dyn + 128*ALD;           // [128][ALD]

    const int tid  = threadIdx.x;
    const int wid  = tid >> 5;
    const int lane = tid & 31;
    const int row0 = blockIdx.x * 128;

    // ---- stage B: w_out fp32 -> fp16 smem ----
#pragma unroll
    for (int it = 0; it < 16; it++) {
        int idx = tid + it * 256;
        int k = idx >> 5, c4 = (idx & 31) << 2;
        float4 v = *(const float4*)&wout[(size_t)k*C + c4];
        __half2 h0 = __floats2half2_rn(v.x, v.y);
        __half2 h1 = __floats2half2_rn(v.z, v.w);
        uint2 o; o.x = *(unsigned*)&h0; o.y = *(unsigned*)&h1;
        *(uint2*)&b_h[k*ALD + c4] = o;
    }

    // ---- Phase A: pool. 16 lanes per row (8 ch/lane), 2 rows per warp-load,
    //      half-warps split k, shfl_xor combine, 2-pt interleave. ----
    {
        const int lh   = lane & 15;
        const int hsel = lane >> 4;
        const int c0   = lh << 3;                   // 8 channels

        const float4 a0a = *(const float4*)&g_A[c0];
        const float4 a0b = *(const float4*)&g_A[c0 + 4];
        const float4 a1a = *(const float4*)&g_A[C + c0];
        const float4 a1b = *(const float4*)&g_A[C + c0 + 4];
        const float4 a2a = *(const float4*)&g_A[2*C + c0];
        const float4 a2b = *(const float4*)&g_A[2*C + c0 + 4];
        const float4 b2a = *(const float4*)&g_b2[c0];
        const float4 b2b = *(const float4*)&g_b2[c0 + 4];
        const float4 wf0 = *(const float4*)&g_wd[c0];
        const float4 wf1 = *(const float4*)&g_wd[c0 + 4];
        __half2 wdh[4];
        wdh[0] = __floats2half2_rn(wf0.x, wf0.y);
        wdh[1] = __floats2half2_rn(wf0.z, wf0.w);
        wdh[2] = __floats2half2_rn(wf1.x, wf1.y);
        wdh[3] = __floats2half2_rn(wf1.z, wf1.w);
        const __half2 ninf = __half2half2(__ushort_as_half(0xFC00));
        const __half* hs = &g_h[0];

        for (int t = 0; t < 16; t += 2) {
            const int pl0 = wid * 16 + t;
            const int pl1 = pl0 + 1;
            const int pt0 = row0 + pl0;
            const int pt1 = row0 + pl1;
            const int base = (pt0 >> 14) << 14;

            const float cx0 = pts[pt0*3 + 0], cy0 = pts[pt0*3 + 1], cz0 = pts[pt0*3 + 2];
            const float cx1 = pts[pt1*3 + 0], cy1 = pts[pt1*3 + 1], cz1 = pts[pt1*3 + 2];

            int j0 = gidx[pt0*KNB + lane] + base;   // fits in 16 bits (< 49152)
            int j1 = gidx[pt1*KNB + lane] + base;
            const float* gp0 = &pts[(size_t)j0*3];
            const float* gp1 = &pts[(size_t)j1*3];
            float dx0 = gp0[0] - cx0, dy0 = gp0[1] - cy0, dz0 = gp0[2] - cz0;
            float dx1 = gp1[0] - cx1, dy1 = gp1[1] - cy1, dz1 = gp1[2] - cz1;
            float dist0 = sqrtf(fmaf(dx0, dx0, fmaf(dy0, dy0, dz0*dz0)));
            float dist1 = sqrtf(fmaf(dx1, dx1, fmaf(dy1, dy1, dz1*dz1)));

            unsigned p0 = (unsigned)j0
                        | ((unsigned)__half_as_ushort(__float2half_rn(dist0)) << 16);
            unsigned p1 = (unsigned)j1
                        | ((unsigned)__half_as_ushort(__float2half_rn(dist1)) << 16);

            __half2 acc0[4], acc1[4];
#pragma unroll
            for (int q = 0; q < 4; q++) { acc0[q] = ninf; acc1[q] = ninf; }

#pragma unroll
            for (int i = 0; i < 16; i++) {
                int src = 2*i + hsel;
                unsigned q0 = __shfl_sync(0xffffffffu, p0, src);
                unsigned q1 = __shfl_sync(0xffffffffu, p1, src);
                __half2 d0 = __half2half2(__ushort_as_half((unsigned short)(q0 >> 16)));
                __half2 d1 = __half2half2(__ushort_as_half((unsigned short)(q1 >> 16)));
                uint4 r0 = *(const uint4*)(hs + (((q0 & 0xFFFFu) << 7) + c0));
                uint4 r1 = *(const uint4*)(hs + (((q1 & 0xFFFFu) << 7) + c0));
                acc0[0] = __hmax2(acc0[0], __hfma2(d0, wdh[0], *(__half2*)&r0.x));
                acc0[1] = __hmax2(acc0[1], __hfma2(d0, wdh[1], *(__half2*)&r0.y));
                acc0[2] = __hmax2(acc0[2], __hfma2(d0, wdh[2], *(__half2*)&r0.z));
                acc0[3] = __hmax2(acc0[3], __hfma2(d0, wdh[3], *(__half2*)&r0.w));
                acc1[0] = __hmax2(acc1[0], __hfma2(d1, wdh[0], *(__half2*)&r1.x));
                acc1[1] = __hmax2(acc1[1], __hfma2(d1, wdh[1], *(__half2*)&r1.y));
                acc1[2] = __hmax2(acc1[2], __hfma2(d1, wdh[2], *(__half2*)&r1.z));
                acc1[3] = __hmax2(acc1[3], __hfma2(d1, wdh[3], *(__half2*)&r1.w));
            }

            // combine the two half-warps' k-subsets
#pragma unroll
            for (int q = 0; q < 4; q++) {
                unsigned u0 = __shfl_xor_sync(0xffffffffu, *(unsigned*)&acc0[q], 16);
                unsigned u1 = __shfl_xor_sync(0xffffffffu, *(unsigned*)&acc1[q], 16);
                acc0[q] = __hmax2(acc0[q], *(__half2*)&u0);
                acc1[q] = __hmax2(acc1[q], *(__half2*)&u1);
            }

            if (hsel == 0) {
                float2 m0[4], m1[4];
#pragma unroll
                for (int q = 0; q < 4; q++) {
                    m0[q] = __half22float2(acc0[q]);
                    m1[q] = __half22float2(acc1[q]);
                }
                const float4 f0a = *(const float4*)&feat[(size_t)pt0*C + c0];
                const float4 f0b = *(const float4*)&feat[(size_t)pt0*C + c0 + 4];
                const float4 f1a = *(const float4*)&feat[(size_t)pt1*C + c0];
                const float4 f1b = *(const float4*)&feat[(size_t)pt1*C + c0 + 4];

                float r0[8], r1[8];
                r0[0] = fmaxf(m0[0].x + fmaf(cx0, a0a.x, fmaf(cy0, a1a.x, fmaf(cz0, a2a.x, b2a.x))), 0.f) + f0a.x;
                r0[1] = fmaxf(m0[0].y + fmaf(cx0, a0a.y, fmaf(cy0, a1a.y, fmaf(cz0, a2a.y, b2a.y))), 0.f) + f0a.y;
                r0[2] = fmaxf(m0[1].x + fmaf(cx0, a0a.z, fmaf(cy0, a1a.z, fmaf(cz0, a2a.z, b2a.z))), 0.f) + f0a.z;
                r0[3] = fmaxf(m0[1].y + fmaf(cx0, a0a.w, fmaf(cy0, a1a.w, fmaf(cz0, a2a.w, b2a.w))), 0.f) + f0a.w;
                r0[4] = fmaxf(m0[2].x + fmaf(cx0, a0b.x, fmaf(cy0, a1b.x, fmaf(cz0, a2b.x, b2b.x))), 0.f) + f0b.x;
                r0[5] = fmaxf(m0[2].y + fmaf(cx0, a0b.y, fmaf(cy0, a1b.y, fmaf(cz0, a2b.y, b2b.y))), 0.f) + f0b.y;
                r0[6] = fmaxf(m0[3].x + fmaf(cx0, a0b.z, fmaf(cy0, a1b.z, fmaf(cz0, a2b.z, b2b.z))), 0.f) + f0b.z;
                r0[7] = fmaxf(m0[3].y + fmaf(cx0, a0b.w, fmaf(cy0, a1b.w, fmaf(cz0, a2b.w, b2b.w))), 0.f) + f0b.w;
                r1[0] = fmaxf(m1[0].x + fmaf(cx1, a0a.x, fmaf(cy1, a1a.x, fmaf(cz1, a2a.x, b2a.x))), 0.f) + f1a.x;
                r1[1] = fmaxf(m1[0].y + fmaf(cx1, a0a.y, fmaf(cy1, a1a.y, fmaf(cz1, a2a.y, b2a.y))), 0.f) + f1a.y;
                r1[2] = fmaxf(m1[1].x + fmaf(cx1, a0a.z, fmaf(cy1, a1a.z, fmaf(cz1, a2a.z, b2a.z))), 0.f) + f1a.z;
                r1[3] = fmaxf(m1[1].y + fmaf(cx1, a0a.w, fmaf(cy1, a1a.w, fmaf(cz1, a2a.w, b2a.w))), 0.f) + f1a.w;
                r1[4] = fmaxf(m1[2].x + fmaf(cx1, a0b.x, fmaf(cy1, a1b.x, fmaf(cz1, a2b.x, b2b.x))), 0.f) + f1b.x;
                r1[5] = fmaxf(m1[2].y + fmaf(cx1, a0b.y, fmaf(cy1, a1b.y, fmaf(cz1, a2b.y, b2b.y))), 0.f) + f1b.y;
                r1[6] = fmaxf(m1[3].x + fmaf(cx1, a0b.z, fmaf(cy1, a1b.z, fmaf(cz1, a2b.z, b2b.z))), 0.f) + f1b.z;
                r1[7] = fmaxf(m1[3].y + fmaf(cx1, a0b.w, fmaf(cy1, a1b.w, fmaf(cz1, a2b.w, b2b.w))), 0.f) + f1b.w;

                __half2 h0 = __floats2half2_rn(r0[0], r0[1]);
                __half2 h1 = __floats2half2_rn(r0[2], r0[3]);
                __half2 h2 = __floats2half2_rn(r0[4], r0[5]);
                __half2 h3 = __floats2half2_rn(r0[6], r0[7]);
                uint4 o0;
                o0.x = *(unsigned*)&h0; o0.y = *(unsigned*)&h1;
                o0.z = *(unsigned*)&h2; o0.w = *(unsigned*)&h3;
                *(uint4*)&a_h[pl0*ALD + c0] = o0;
                __half2 g0 = __floats2half2_rn(r1[0], r1[1]);
                __half2 g1 = __floats2half2_rn(r1[2], r1[3]);
                __half2 g2 = __floats2half2_rn(r1[4], r1[5]);
                __half2 g3 = __floats2half2_rn(r1[6], r1[7]);
                uint4 o1;
                o1.x = *(unsigned*)&g0; o1.y = *(unsigned*)&g1;
                o1.z = *(unsigned*)&g2; o1.w = *(unsigned*)&g3;
                *(uint4*)&a_h[pl1*ALD + c0] = o1;
            }
        }
    }
    __syncthreads();

    // ---- Phase B: wmma GEMM res @ w_out ----
    const int wm = wid >> 1;
    const int wn = wid & 1;

    wmma::fragment<wmma::accumulator, 16, 16, 16, float> acc[2][4];
#pragma unroll
    for (int i = 0; i < 2; i++)
#pragma unroll
        for (int j = 0; j < 4; j++) wmma::fill_fragment(acc[i][j], 0.f);

#pragma unroll
    for (int kk = 0; kk < 8; kk++) {
        wmma::fragment<wmma::matrix_a, 16, 16, 16, __half, wmma::row_major> af[2];
        wmma::fragment<wmma::matrix_b, 16, 16, 16, __half, wmma::row_major> bf[4];
#pragma unroll
        for (int i = 0; i < 2; i++)
            wmma::load_matrix_sync(af[i], &a_h[(wm*32 + i*16)*ALD + kk*16], ALD);
#pragma unroll
        for (int j = 0; j < 4; j++)
            wmma::load_matrix_sync(bf[j], &b_h[(kk*16)*ALD + wn*64 + j*16], ALD);
#pragma unroll
        for (int i = 0; i < 2; i++)
#pragma unroll
            for (int j = 0; j < 4; j++)
                wmma::mma_sync(acc[i][j], af[i], bf[j], acc[i][j]);
    }
    __syncthreads();

    // ---- Phase C: frags -> fp32 smem, bias + LN (256-thread stats) + relu ----
    float* c_sm = (float*)dyn;                      // [128][CLD]
    float* smu  = (float*)dyn + 128*CLD;            // [128]
    float* srs  = smu + 128;                        // [128]
    float* sp   = srs + 128;                        // [256]
    float* sq   = sp + 256;                         // [256]

#pragma unroll
    for (int i = 0; i < 2; i++)
#pragma unroll
        for (int j = 0; j < 4; j++)
            wmma::store_matrix_sync(&c_sm[(wm*32 + i*16)*CLD + wn*64 + j*16],
                                    acc[i][j], CLD, wmma::mem_row_major);
    __syncthreads();

    {
        int r = tid & 127, half = tid >> 7;
        int cbeg = half * 64;
        float sum = 0.f, ss = 0.f;
#pragma unroll 8
        for (int c = cbeg; c < cbeg + 64; c += 4) {
            float4 x = *(const float4*)&c_sm[r*CLD + c];
            float4 b = *(const float4*)&bout[c];
            float v0 = x.x + b.x, v1 = x.y + b.y, v2 = x.z + b.z, v3 = x.w + b.w;
            sum += v0 + v1 + v2 + v3;
            ss = fmaf(v0, v0, fmaf(v1, v1, fmaf(v2, v2, fmaf(v3, v3, ss))));
        }
        sp[tid] = sum; sq[tid] = ss;
    }
    __syncthreads();
    if (tid < 128) {
        float sum = sp[tid] + sp[tid + 128];
        float ss  = sq[tid] + sq[tid + 128];
        float mu  = sum * (1.f/128.f);
        float var = fmaf(ss, 1.f/128.f, -mu*mu);
        smu[tid] = mu;
        srs[tid] = rsqrtf(var + LN_EPS);
    }
    __syncthreads();

#pragma unroll
    for (int it = 0; it < 16; it++) {
        int idx = tid + it * 256;
        int r = idx >> 5, c4 = (idx & 31) << 2;
        float4 x = *(const float4*)&c_sm[r*CLD + c4];
        float4 bb = *(const float4*)&bout[c4];
        float4 g = *(const float4*)&lng[c4];
        float4 lb = *(const float4*)&lnb[c4];
        float mu = smu[r], rs = srs[r];
        float4 y;
        y.x = fmaxf(fmaf((x.x + bb.x - mu) * rs, g.x, lb.x), 0.f);
        y.y = fmaxf(fmaf((x.y + bb.y - mu) * rs, g.y, lb.y), 0.f);
        y.z = fmaxf(fmaf((x.z + bb.z - mu) * rs, g.z, lb.z), 0.f);
        y.w = fmaxf(fmaf((x.w + bb.w - mu) * rs, g.w, lb.w), 0.f);
        *(float4*)&out[(size_t)(row0 + r)*C + c4] = y;
    }
}

// ---------------------------------------------------------------------------
extern "C" void kernel_launch(void* const* d_in, const int* in_sizes, int n_in,
                              void* d_out, int out_size)
{
    const float* points = (const float*)d_in[0];
    const float* feat   = (const float*)d_in[1];
    const int*   gidx   = (const int*)  d_in[2];
    const float* w_pos  = (const float*)d_in[3];
    const float* b_pos  = (const float*)d_in[4];
    const float* w_gcm  = (const float*)d_in[5];
    const float* b_gcm  = (const float*)d_in[6];
    const float* w_out  = (const float*)d_in[7];
    const float* b_out  = (const float*)d_in[8];
    const float* ln_g   = (const float*)d_in[9];
    const float* ln_b   = (const float*)d_in[10];
    float* out = (float*)d_out;

    cudaFuncSetAttribute(k_gemm_s, cudaFuncAttributeMaxDynamicSharedMemorySize, GS_SMEM);
    cudaFuncSetAttribute(k_fused,  cudaFuncAttributeMaxDynamicSharedMemorySize, FUSED_SMEM);

    k_gemm_s<<<MTOT/128, 256, GS_SMEM>>>(feat, w_gcm, points, w_pos, b_pos, b_gcm);
    k_fused <<<MTOT/128, 256, FUSED_SMEM>>>(points, feat, gidx,
                                            w_out, b_out, ln_g, ln_b, out);
}

// round 12
// speedup vs baseline: 1.2067x; 1.0294x over previous
#include <cuda_runtime.h>
#include <cuda_fp16.h>
#include <mma.h>
#include <math.h>
#include <stdint.h>

using namespace nvcuda;

#define BATCH 2
#define NPTS  16384
#define KNB   32
#define C     128
#define MTOT  (BATCH*NPTS)   // 32768
#define LN_EPS 1e-5f

// scratch (device globals; no runtime allocation)
__device__ __half g_h [(size_t)MTOT*C];   // 8 MB, s in fp16
__device__ __half g_r [(size_t)MTOT*C];   // 8 MB, res in fp16
__device__ float  g_A [3*C];
__device__ float  g_wd[C];
__device__ float  g_b2[C];

#define ALD 136                     // a/b smem pitch in halves (272 B)
#define CLD 132                     // c  smem pitch in floats (528 B)
#define GS_SMEM  (2 * 128 * ALD * 2)                        // 69632 B
#define LN_SMEM  ((128*CLD + 128 + 128 + 256 + 256) * 4)    // 70656 B

// ---------------------------------------------------------------------------
// K1 (wmma): s = (feat + pts·wp_nbr) @ w_gcm -> fp16 g_h.
// CTA 0 additionally computes pool constants g_A/g_wd/g_b2 afterwards.
// ---------------------------------------------------------------------------
__global__ __launch_bounds__(256, 2) void k_gemm_s(
    const float* __restrict__ feat, const float* __restrict__ wg,
    const float* __restrict__ pts,
    const float* __restrict__ w_pos, const float* __restrict__ b_pos,
    const float* __restrict__ b_gcm)
{
    extern __shared__ char dyn[];
    __half* a_sm = (__half*)dyn;                    // [128][ALD]
    __half* b_sm = (__half*)dyn + 128*ALD;          // [128][ALD]

    __shared__ float wp_c[3][C];

    const int tid  = threadIdx.x;
    const int wid  = tid >> 5;
    const int row0 = blockIdx.x * 128;

    if (tid < C) {
#pragma unroll
        for (int d = 0; d < 3; d++)
            wp_c[d][tid] = w_pos[(3+d)*C + tid] + w_pos[(6+d)*C + tid];
    }
    __syncthreads();

    // stage A = fp16(feat + pts·wp_c), B = fp16(w_gcm)
#pragma unroll
    for (int it = 0; it < 16; it++) {
        int idx = tid + it * 256;
        int r = idx >> 5, c4 = (idx & 31) << 2;
        int gr = row0 + r;
        float4 v = *(const float4*)&feat[(size_t)gr*C + c4];
        float px = pts[gr*3 + 0], py = pts[gr*3 + 1], pz = pts[gr*3 + 2];
        float4 w0 = *(const float4*)&wp_c[0][c4];
        float4 w1 = *(const float4*)&wp_c[1][c4];
        float4 w2 = *(const float4*)&wp_c[2][c4];
        v.x = fmaf(px, w0.x, fmaf(py, w1.x, fmaf(pz, w2.x, v.x)));
        v.y = fmaf(px, w0.y, fmaf(py, w1.y, fmaf(pz, w2.y, v.y)));
        v.z = fmaf(px, w0.z, fmaf(py, w1.z, fmaf(pz, w2.z, v.z)));
        v.w = fmaf(px, w0.w, fmaf(py, w1.w, fmaf(pz, w2.w, v.w)));
        __half2 h0 = __floats2half2_rn(v.x, v.y);
        __half2 h1 = __floats2half2_rn(v.z, v.w);
        uint2 o; o.x = *(unsigned*)&h0; o.y = *(unsigned*)&h1;
        *(uint2*)&a_sm[r*ALD + c4] = o;

        float4 w = *(const float4*)&wg[(size_t)r*C + c4];
        __half2 q0 = __floats2half2_rn(w.x, w.y);
        __half2 q1 = __floats2half2_rn(w.z, w.w);
        uint2 ow; ow.x = *(unsigned*)&q0; ow.y = *(unsigned*)&q1;
        *(uint2*)&b_sm[r*ALD + c4] = ow;
    }
    __syncthreads();

    const int wm = wid >> 1;
    const int wn = wid & 1;

    wmma::fragment<wmma::accumulator, 16, 16, 16, float> acc[2][4];
#pragma unroll
    for (int i = 0; i < 2; i++)
#pragma unroll
        for (int j = 0; j < 4; j++) wmma::fill_fragment(acc[i][j], 0.f);

#pragma unroll
    for (int kk = 0; kk < 8; kk++) {
        wmma::fragment<wmma::matrix_a, 16, 16, 16, __half, wmma::row_major> af[2];
        wmma::fragment<wmma::matrix_b, 16, 16, 16, __half, wmma::row_major> bf[4];
#pragma unroll
        for (int i = 0; i < 2; i++)
            wmma::load_matrix_sync(af[i], &a_sm[(wm*32 + i*16)*ALD + kk*16], ALD);
#pragma unroll
        for (int j = 0; j < 4; j++)
            wmma::load_matrix_sync(bf[j], &b_sm[(kk*16)*ALD + wn*64 + j*16], ALD);
#pragma unroll
        for (int i = 0; i < 2; i++)
#pragma unroll
            for (int j = 0; j < 4; j++)
                wmma::mma_sync(acc[i][j], af[i], bf[j], acc[i][j]);
    }
    __syncthreads();

    float* c_sm = (float*)dyn;                      // [128][CLD]
#pragma unroll
    for (int i = 0; i < 2; i++)
#pragma unroll
        for (int j = 0; j < 4; j++)
            wmma::store_matrix_sync(&c_sm[(wm*32 + i*16)*CLD + wn*64 + j*16],
                                    acc[i][j], CLD, wmma::mem_row_major);
    __syncthreads();

#pragma unroll
    for (int it = 0; it < 16; it++) {
        int idx = tid + it * 256;
        int r = idx >> 5, c4 = (idx & 31) << 2;
        float4 v = *(const float4*)&c_sm[r*CLD + c4];
        __half2 h0 = __floats2half2_rn(v.x, v.y);
        __half2 h1 = __floats2half2_rn(v.z, v.w);
        uint2 o; o.x = *(unsigned*)&h0; o.y = *(unsigned*)&h1;
        *(uint2*)&g_h[(size_t)(row0 + r)*C + c4] = o;
    }

    // ---- CTA 0: pool constants (fp32) ----
    if (blockIdx.x == 0) {
        float* part = (float*)dyn;  // reuse smem: 8*256 floats (post-sync)
        __syncthreads();
        const int cc   = tid & 127;
        const int half = tid >> 7;
        const int j0   = half * 64;
        float q[8];
#pragma unroll
        for (int i = 0; i < 8; i++) q[i] = 0.f;
#pragma unroll 4
        for (int jj = 0; jj < 64; jj++) {
            int j = j0 + jj;
            float w = wg[(size_t)j*C + cc];
            q[0] = fmaf(w_pos[0*C + j], w, q[0]);
            q[1] = fmaf(w_pos[1*C + j], w, q[1]);
            q[2] = fmaf(w_pos[2*C + j], w, q[2]);
            q[3] = fmaf(w_pos[6*C + j], w, q[3]);
            q[4] = fmaf(w_pos[7*C + j], w, q[4]);
            q[5] = fmaf(w_pos[8*C + j], w, q[5]);
            q[6] = fmaf(w_pos[9*C + j], w, q[6]);
            q[7] = fmaf(b_pos[j],       w, q[7]);
        }
#pragma unroll
        for (int i = 0; i < 8; i++) part[i*256 + tid] = q[i];
        __syncthreads();
        if (tid < 128) {
            float r[8];
#pragma unroll
            for (int i = 0; i < 8; i++)
                r[i] = part[i*256 + tid] + part[i*256 + tid + 128];
            g_A[0*C + tid] = r[0] - r[3];
            g_A[1*C + tid] = r[1] - r[4];
            g_A[2*C + tid] = r[2] - r[5];
            g_wd[tid]      = r[6];
            g_b2[tid]      = r[7] + b_gcm[tid];
        }
    }
}

// ---------------------------------------------------------------------------
// K2 (pool, standalone, high occupancy): one warp per point, lane = 4 ch.
// res = relu(max_k(s[j_k] + d_k*wd) + u) + feat  -> fp16 g_r.
// No smem, low regs -> many CTAs/SM to hide L2 gather latency.
// ---------------------------------------------------------------------------
__global__ __launch_bounds__(256) void k_pool(
    const float* __restrict__ pts, const float* __restrict__ feat,
    const int*   __restrict__ gidx)
{
    const int pt   = (blockIdx.x * 256 + threadIdx.x) >> 5;  // 0..32767
    const int lane = threadIdx.x & 31;
    const int base = (pt >> 14) << 14;
    const int c0   = lane << 2;                 // 4 channels per lane

    const float4 wf = *(const float4*)&g_wd[c0];
    const __half2 wd01 = __floats2half2_rn(wf.x, wf.y);
    const __half2 wd23 = __floats2half2_rn(wf.z, wf.w);
    const __half2 ninf = __half2half2(__ushort_as_half(0xFC00));
    const __half* hs = &g_h[0];

    const float cx = pts[pt*3 + 0], cy = pts[pt*3 + 1], cz = pts[pt*3 + 2];
    int j = gidx[pt*KNB + lane] + base;          // < 49152, fits 16 bits
    const float* gp = &pts[(size_t)j*3];
    float dx = gp[0] - cx, dy = gp[1] - cy, dz = gp[2] - cz;
    float dist = sqrtf(fmaf(dx, dx, fmaf(dy, dy, dz*dz)));
    unsigned p = (unsigned)j
               | ((unsigned)__half_as_ushort(__float2half_rn(dist)) << 16);

    __half2 acc01 = ninf, acc23 = ninf;
#pragma unroll
    for (int k = 0; k < 32; k++) {
        unsigned q = __shfl_sync(0xffffffffu, p, k);
        __half2 d = __half2half2(__ushort_as_half((unsigned short)(q >> 16)));
        uint2 rv = *(const uint2*)(hs + (((q & 0xFFFFu) << 7) + c0));
        acc01 = __hmax2(acc01, __hfma2(d, wd01, *(__half2*)&rv.x));
        acc23 = __hmax2(acc23, __hfma2(d, wd23, *(__half2*)&rv.y));
    }

    float2 m01 = __half22float2(acc01);
    float2 m23 = __half22float2(acc23);

    const float4 a0 = *(const float4*)&g_A[c0];
    const float4 a1 = *(const float4*)&g_A[C + c0];
    const float4 a2 = *(const float4*)&g_A[2*C + c0];
    const float4 b2 = *(const float4*)&g_b2[c0];
    const float4 f  = *(const float4*)&feat[(size_t)pt*C + c0];

    float r0 = fmaxf(m01.x + fmaf(cx, a0.x, fmaf(cy, a1.x, fmaf(cz, a2.x, b2.x))), 0.f) + f.x;
    float r1 = fmaxf(m01.y + fmaf(cx, a0.y, fmaf(cy, a1.y, fmaf(cz, a2.y, b2.y))), 0.f) + f.y;
    float r2 = fmaxf(m23.x + fmaf(cx, a0.z, fmaf(cy, a1.z, fmaf(cz, a2.z, b2.z))), 0.f) + f.z;
    float r3 = fmaxf(m23.y + fmaf(cx, a0.w, fmaf(cy, a1.w, fmaf(cz, a2.w, b2.w))), 0.f) + f.w;

    __half2 h0 = __floats2half2_rn(r0, r1);
    __half2 h1 = __floats2half2_rn(r2, r3);
    uint2 o; o.x = *(unsigned*)&h0; o.y = *(unsigned*)&h1;
    *(uint2*)&g_r[(size_t)pt*C + c0] = o;
}

// ---------------------------------------------------------------------------
// K3 (wmma + LN): out = relu(LN(res @ w_out + b_out)·g + b).
// A staged from g_r by straight fp16 copy; B from w_out with conversion.
// ---------------------------------------------------------------------------
__global__ __launch_bounds__(256, 2) void k_gemm_ln(
    const float* __restrict__ wout, const float* __restrict__ bout,
    const float* __restrict__ lng,  const float* __restrict__ lnb,
    float* __restrict__ out)
{
    extern __shared__ char dyn[];
    __half* a_h = (__half*)dyn;                     // [128][ALD]
    __half* b_h = (__half*)dyn + 128*ALD;           // [128][ALD]

    const int tid  = threadIdx.x;
    const int wid  = tid >> 5;
    const int row0 = blockIdx.x * 128;

    // stage A: straight uint4 copy of fp16 res rows
#pragma unroll
    for (int it = 0; it < 8; it++) {
        int idx = tid + it * 256;            // 2048 uint4s over 128x128 halves
        int r = idx >> 4, c8 = (idx & 15) << 3;
        uint4 v = *(const uint4*)&g_r[(size_t)(row0 + r)*C + c8];
        *(uint4*)&a_h[r*ALD + c8] = v;
    }
    // stage B: w_out fp32 -> fp16
#pragma unroll
    for (int it = 0; it < 16; it++) {
        int idx = tid + it * 256;
        int k = idx >> 5, c4 = (idx & 31) << 2;
        float4 v = *(const float4*)&wout[(size_t)k*C + c4];
        __half2 h0 = __floats2half2_rn(v.x, v.y);
        __half2 h1 = __floats2half2_rn(v.z, v.w);
        uint2 o; o.x = *(unsigned*)&h0; o.y = *(unsigned*)&h1;
        *(uint2*)&b_h[k*ALD + c4] = o;
    }
    __syncthreads();

    const int wm = wid >> 1;
    const int wn = wid & 1;

    wmma::fragment<wmma::accumulator, 16, 16, 16, float> acc[2][4];
#pragma unroll
    for (int i = 0; i < 2; i++)
#pragma unroll
        for (int j = 0; j < 4; j++) wmma::fill_fragment(acc[i][j], 0.f);

#pragma unroll
    for (int kk = 0; kk < 8; kk++) {
        wmma::fragment<wmma::matrix_a, 16, 16, 16, __half, wmma::row_major> af[2];
        wmma::fragment<wmma::matrix_b, 16, 16, 16, __half, wmma::row_major> bf[4];
#pragma unroll
        for (int i = 0; i < 2; i++)
            wmma::load_matrix_sync(af[i], &a_h[(wm*32 + i*16)*ALD + kk*16], ALD);
#pragma unroll
        for (int j = 0; j < 4; j++)
            wmma::load_matrix_sync(bf[j], &b_h[(kk*16)*ALD + wn*64 + j*16], ALD);
#pragma unroll
        for (int i = 0; i < 2; i++)
#pragma unroll
            for (int j = 0; j < 4; j++)
                wmma::mma_sync(acc[i][j], af[i], bf[j], acc[i][j]);
    }
    __syncthreads();

    // epilogue: frags -> fp32 smem, bias + LN (256-thread stats) + relu
    float* c_sm = (float*)dyn;                      // [128][CLD]
    float* smu  = (float*)dyn + 128*CLD;            // [128]
    float* srs  = smu + 128;                        // [128]
    float* sp   = srs + 128;                        // [256]
    float* sq   = sp + 256;                         // [256]

#pragma unroll
    for (int i = 0; i < 2; i++)
#pragma unroll
        for (int j = 0; j < 4; j++)
            wmma::store_matrix_sync(&c_sm[(wm*32 + i*16)*CLD + wn*64 + j*16],
                                    acc[i][j], CLD, wmma::mem_row_major);
    __syncthreads();

    {
        int r = tid & 127, half = tid >> 7;
        int cbeg = half * 64;
        float sum = 0.f, ss = 0.f;
#pragma unroll 8
        for (int c = cbeg; c < cbeg + 64; c += 4) {
            float4 x = *(const float4*)&c_sm[r*CLD + c];
            float4 b = *(const float4*)&bout[c];
            float v0 = x.x + b.x, v1 = x.y + b.y, v2 = x.z + b.z, v3 = x.w + b.w;
            sum += v0 + v1 + v2 + v3;
            ss = fmaf(v0, v0, fmaf(v1, v1, fmaf(v2, v2, fmaf(v3, v3, ss))));
        }
        sp[tid] = sum; sq[tid] = ss;
    }
    __syncthreads();
    if (tid < 128) {
        float sum = sp[tid] + sp[tid + 128];
        float ss  = sq[tid] + sq[tid + 128];
        float mu  = sum * (1.f/128.f);
        float var = fmaf(ss, 1.f/128.f, -mu*mu);
        smu[tid] = mu;
        srs[tid] = rsqrtf(var + LN_EPS);
    }
    __syncthreads();

#pragma unroll
    for (int it = 0; it < 16; it++) {
        int idx = tid + it * 256;
        int r = idx >> 5, c4 = (idx & 31) << 2;
        float4 x = *(const float4*)&c_sm[r*CLD + c4];
        float4 bb = *(const float4*)&bout[c4];
        float4 g = *(const float4*)&lng[c4];
        float4 lb = *(const float4*)&lnb[c4];
        float mu = smu[r], rs = srs[r];
        float4 y;
        y.x = fmaxf(fmaf((x.x + bb.x - mu) * rs, g.x, lb.x), 0.f);
        y.y = fmaxf(fmaf((x.y + bb.y - mu) * rs, g.y, lb.y), 0.f);
        y.z = fmaxf(fmaf((x.z + bb.z - mu) * rs, g.z, lb.z), 0.f);
        y.w = fmaxf(fmaf((x.w + bb.w - mu) * rs, g.w, lb.w), 0.f);
        *(float4*)&out[(size_t)(row0 + r)*C + c4] = y;
    }
}

// ---------------------------------------------------------------------------
extern "C" void kernel_launch(void* const* d_in, const int* in_sizes, int n_in,
                              void* d_out, int out_size)
{
    const float* points = (const float*)d_in[0];
    const float* feat   = (const float*)d_in[1];
    const int*   gidx   = (const int*)  d_in[2];
    const float* w_pos  = (const float*)d_in[3];
    const float* b_pos  = (const float*)d_in[4];
    const float* w_gcm  = (const float*)d_in[5];
    const float* b_gcm  = (const float*)d_in[6];
    const float* w_out  = (const float*)d_in[7];
    const float* b_out  = (const float*)d_in[8];
    const float* ln_g   = (const float*)d_in[9];
    const float* ln_b   = (const float*)d_in[10];
    float* out = (float*)d_out;

    cudaFuncSetAttribute(k_gemm_s,  cudaFuncAttributeMaxDynamicSharedMemorySize, GS_SMEM);
    cudaFuncSetAttribute(k_gemm_ln, cudaFuncAttributeMaxDynamicSharedMemorySize, LN_SMEM);

    k_gemm_s <<<MTOT/128,    256, GS_SMEM>>>(feat, w_gcm, points, w_pos, b_pos, b_gcm);
    k_pool   <<<MTOT*32/256, 256>>>(points, feat, gidx);
    k_gemm_ln<<<MTOT/128,    256, LN_SMEM>>>(w_out, b_out, ln_g, ln_b, out);
}